// round 4
// baseline (speedup 1.0000x reference)
#include <cuda_runtime.h>
#include <cstdint>

// ---------------------------------------------------------------------------
// C[4096,18432] = A[4096,7168] * W[18432,7168]^T, per-128x128 block scales.
//  Pass 1: pack kernels -> dequant + cvt.rna.tf32, FRAGMENT-MAJOR layout
//          (each lane's mma.sync fragment registers contiguous 16B).
//  Pass 2: GEMM -> mma.sync.m16n8k8 tf32, cp.async 4-stage pipeline,
//          mainloop uses only ld.shared.v4 (conflict-free).
// ---------------------------------------------------------------------------

#define MDIM 4096
#define NDIM 18432
#define KDIM 7168
#define BM 128
#define BN 256
#define BK 32
#define KCHUNKS (KDIM / BK)          // 224
#define MTILES (MDIM / BM)           // 32
#define NTILES (NDIM / BN)           // 72

#define A_TILE_BYTES (BM * 128)      // 16384
#define W_TILE_BYTES (BN * 128)      // 32768
#define STAGE_BYTES  (A_TILE_BYTES + W_TILE_BYTES)        // 49152
#define SMEM_TILE0   1024
#define SMEM_TOTAL   (SMEM_TILE0 + 4 * STAGE_BYTES)       // 197632

__device__ __align__(1024) unsigned char g_ap[(size_t)MDIM * KDIM * 4];
__device__ __align__(1024) unsigned char g_wp[(size_t)NDIM * KDIM * 4];

// ---------------------------------------------------------------------------
__device__ __forceinline__ uint32_t smem_u32(const void* p) {
    uint32_t a;
    asm("{ .reg .u64 t; cvta.to.shared.u64 t, %1; cvt.u32.u64 %0, t; }" : "=r"(a) : "l"(p));
    return a;
}
__device__ __forceinline__ float rna_tf32(float x) {
    uint32_t u;
    asm("cvt.rna.tf32.f32 %0, %1;" : "=r"(u) : "f"(x));
    return __uint_as_float(u);
}
__device__ __forceinline__ uint4 lds128(uint32_t a) {
    uint4 v;
    asm volatile("ld.shared.v4.b32 {%0,%1,%2,%3}, [%4];"
                 : "=r"(v.x), "=r"(v.y), "=r"(v.z), "=r"(v.w) : "r"(a));
    return v;
}
__device__ __forceinline__ void cp16(uint32_t dst, const void* src) {
    asm volatile("cp.async.cg.shared.global [%0], [%1], 16;"
                 :: "r"(dst), "l"(__cvta_generic_to_global(src)) : "memory");
}
__device__ __forceinline__ void mma_tf32(float* d, const uint4& a, uint32_t b0, uint32_t b1) {
    asm volatile(
        "mma.sync.aligned.m16n8k8.row.col.f32.tf32.tf32.f32 "
        "{%0,%1,%2,%3}, {%4,%5,%6,%7}, {%8,%9}, {%0,%1,%2,%3};"
        : "+f"(d[0]), "+f"(d[1]), "+f"(d[2]), "+f"(d[3])
        : "r"(a.x), "r"(a.y), "r"(a.z), "r"(a.w), "r"(b0), "r"(b1));
}

// ---------------------------------------------------------------------------
// Fragment-major pack layout.
//
// A tile (128 rows x 32 k, 16KB):
//   addr = (((half*4 + ks)*4 + mi)*32 + lane)*16 + reg*4
//   lane = tr*4 + tc;  reg0=(tr,tc) reg1=(tr+8,tc) reg2=(tr,tc+4) reg3=(tr+8,tc+4)
//   row m_in = half*64 + mi*16 + tr(+8), col k_in = ks*8 + tc(+4)
//
// W tile (256 rows x 32 k, 32KB):
//   addr = (((wn*4 + ks)*4 + j)*32 + lane)*16 + slot*4
//   slot0=b0(ni=2j) slot1=b1(2j) slot2=b0(2j+1) slot3=b1(2j+1)
//   row n_in = wn*64 + ni*8 + tr, col k_in = ks*8 + tc (+4 for b1)
// ---------------------------------------------------------------------------
__global__ __launch_bounds__(256) void pack_a_kernel(const float* __restrict__ x) {
    size_t i = (size_t)blockIdx.x * 256 + threadIdx.x;
    if (i >= (size_t)MDIM * KDIM / 4) return;
    size_t f = i * 4;
    int m = (int)(f / KDIM);
    int k = (int)(f % KDIM);
    float4 v = *(const float4*)(x + f);

    int m_in = m & 127, k_in = k & 31;
    int half = m_in >> 6, mrem = m_in & 63;
    int mi = mrem >> 4, r = mrem & 15, tr = r & 7, hi8 = r >> 3;
    int ks = k_in >> 3, khi = (k_in & 7) >> 2;      // k_in multiple of 4
    int reg = hi8 + 2 * khi;

    unsigned char* tile = g_ap + ((size_t)(m >> 7) * KCHUNKS + (k >> 5)) * A_TILE_BYTES;
    uint32_t base = (uint32_t)(((half * 4 + ks) * 4 + mi) * 512 + tr * 64 + reg * 4);
    *(float*)(tile + base +  0) = rna_tf32(v.x);
    *(float*)(tile + base + 16) = rna_tf32(v.y);
    *(float*)(tile + base + 32) = rna_tf32(v.z);
    *(float*)(tile + base + 48) = rna_tf32(v.w);
}

__global__ __launch_bounds__(256) void pack_w_kernel(const float* __restrict__ w,
                                                     const float* __restrict__ scale) {
    size_t i = (size_t)blockIdx.x * 256 + threadIdx.x;
    if (i >= (size_t)NDIM * KDIM / 4) return;
    size_t f = i * 4;
    int n = (int)(f / KDIM);
    int k = (int)(f % KDIM);
    float4 v = *(const float4*)(w + f);
    float s = scale[(size_t)(n >> 7) * (KDIM / 128) + (k >> 7)];

    int n_in = n & 255, k_in = k & 31;
    int wn = n_in >> 6, nrem = n_in & 63;
    int ni = nrem >> 3, tr = nrem & 7, j = ni >> 1, nodd = ni & 1;
    int ks = k_in >> 3, khi = (k_in & 7) >> 2;
    int slot = nodd * 2 + khi;

    unsigned char* tile = g_wp + ((size_t)(n >> 8) * KCHUNKS + (k >> 5)) * W_TILE_BYTES;
    uint32_t base = (uint32_t)(((wn * 4 + ks) * 4 + j) * 512 + tr * 64 + slot * 4);
    *(float*)(tile + base +  0) = rna_tf32(v.x * s);
    *(float*)(tile + base + 16) = rna_tf32(v.y * s);
    *(float*)(tile + base + 32) = rna_tf32(v.z * s);
    *(float*)(tile + base + 48) = rna_tf32(v.w * s);
}

// ---------------------------------------------------------------------------
// GEMM: 8 warps (2m x 4n), warp tile 64x64, mma m16n8k8 tf32.
// ---------------------------------------------------------------------------
__global__ __launch_bounds__(256, 1) void gemm_tf32_kernel(float* __restrict__ C) {
    extern __shared__ __align__(1024) unsigned char smem[];
    const uint32_t sb = smem_u32(smem) + SMEM_TILE0;
    const int tid = threadIdx.x;
    const int wid = tid >> 5;
    const int lane = tid & 31;

    // Grid swizzle: 8-wide n groups for L2 reuse.
    const int GN = 8;
    int bid = blockIdx.x;
    int grp = bid / (MTILES * GN);
    int rem = bid % (MTILES * GN);
    int bm = rem / GN;
    int bn = grp * GN + rem % GN;

    const unsigned char* aP = g_ap + (size_t)bm * KCHUNKS * A_TILE_BYTES;
    const unsigned char* wP = g_wp + (size_t)bn * KCHUNKS * W_TILE_BYTES;

    const int wm = wid & 1;       // m half
    const int wn = wid >> 1;      // n quarter
    const int tr = lane >> 2;
    const int tc = lane & 3;

    // Fragment base addresses (relative to stage base), ks stride = 2048B.
    uint32_t aBase[4], bBase[4];
#pragma unroll
    for (int mi = 0; mi < 4; mi++)
        aBase[mi] = (uint32_t)(((wm * 4) * 4 + mi) * 512 + lane * 16);
#pragma unroll
    for (int j = 0; j < 4; j++)
        bBase[j] = (uint32_t)(A_TILE_BYTES + ((wn * 4) * 4 + j) * 512 + lane * 16);

    float acc[4][8][4];
#pragma unroll
    for (int mi = 0; mi < 4; mi++)
#pragma unroll
        for (int ni = 0; ni < 8; ni++)
#pragma unroll
            for (int q = 0; q < 4; q++) acc[mi][ni][q] = 0.f;

    auto issue = [&](int c) {
        if (c < KCHUNKS) {
            const unsigned char* srcA = aP + (size_t)c * A_TILE_BYTES;
            const unsigned char* srcW = wP + (size_t)c * W_TILE_BYTES;
            uint32_t dst = sb + (c & 3) * STAGE_BYTES;
#pragma unroll
            for (int i = 0; i < 4; i++) {
                int idx = tid + i * 256;
                cp16(dst + idx * 16, srcA + idx * 16);
            }
#pragma unroll
            for (int i = 0; i < 8; i++) {
                int idx = tid + i * 256;
                cp16(dst + A_TILE_BYTES + idx * 16, srcW + idx * 16);
            }
        }
        asm volatile("cp.async.commit_group;" ::: "memory");
    };

    issue(0);
    issue(1);
    issue(2);

#pragma unroll 1
    for (int c = 0; c < KCHUNKS; c++) {
        asm volatile("cp.async.wait_group 2;" ::: "memory");
        __syncthreads();
        // Stage (c+3)&3 == (c-1)&3: every thread has finished computing chunk
        // c-1 before this sync, so refilling it now is safe. Issue before
        // compute to overlap the copy with this chunk's math.
        issue(c + 3);

        const uint32_t st = sb + (c & 3) * STAGE_BYTES;
#pragma unroll
        for (int ks = 0; ks < 4; ks++) {
            uint4 af[4];
#pragma unroll
            for (int mi = 0; mi < 4; mi++)
                af[mi] = lds128(st + aBase[mi] + ks * 2048);
            uint4 bf[4];
#pragma unroll
            for (int j = 0; j < 4; j++)
                bf[j] = lds128(st + bBase[j] + ks * 2048);
#pragma unroll
            for (int mi = 0; mi < 4; mi++)
#pragma unroll
                for (int j = 0; j < 4; j++) {
                    mma_tf32(acc[mi][2 * j],     af[mi], bf[j].x, bf[j].y);
                    mma_tf32(acc[mi][2 * j + 1], af[mi], bf[j].z, bf[j].w);
                }
        }
    }

    // Epilogue: acc[mi][ni] rows bm*128 + wm*64 + mi*16 + tr (+8),
    // cols bn*256 + wn*64 + ni*8 + 2*tc (+1).
#pragma unroll
    for (int mi = 0; mi < 4; mi++) {
        size_t r0 = (size_t)bm * BM + wm * 64 + mi * 16 + tr;
        float* p0 = C + r0 * NDIM + (size_t)bn * BN + wn * 64 + 2 * tc;
        float* p1 = p0 + (size_t)8 * NDIM;
#pragma unroll
        for (int ni = 0; ni < 8; ni++) {
            *(float2*)(p0 + ni * 8) = make_float2(acc[mi][ni][0], acc[mi][ni][1]);
            *(float2*)(p1 + ni * 8) = make_float2(acc[mi][ni][2], acc[mi][ni][3]);
        }
    }
}

// ---------------------------------------------------------------------------
extern "C" void kernel_launch(void* const* d_in, const int* in_sizes, int n_in,
                              void* d_out, int out_size) {
    const float* x      = (const float*)d_in[0];
    const float* weight = (const float*)d_in[1];
    const float* scale  = (const float*)d_in[2];
    float* out          = (float*)d_out;

    cudaFuncSetAttribute(gemm_tf32_kernel,
                         cudaFuncAttributeMaxDynamicSharedMemorySize, SMEM_TOTAL);

    size_t a4 = (size_t)MDIM * KDIM / 4;
    size_t w4 = (size_t)NDIM * KDIM / 4;
    pack_a_kernel<<<(unsigned)((a4 + 255) / 256), 256>>>(x);
    pack_w_kernel<<<(unsigned)((w4 + 255) / 256), 256>>>(weight, scale);
    gemm_tf32_kernel<<<MTILES * NTILES, 256, SMEM_TOTAL>>>(out);
}